// round 16
// baseline (speedup 1.0000x reference)
#include <cuda_runtime.h>
#include <math.h>

#define NSWEEPS_MAX 16
#define N 64
#define NH 32
#define NP 32            // packed row-pairs per column
#define FULLMASK 0xffffffffu
#define CONV_TOL 1e-8f   // on apq^2/(app*aqq)

typedef unsigned long long ull;

__device__ __forceinline__ ull pack2(float lo, float hi) {
    ull r; asm("mov.b64 %0, {%1, %2};" : "=l"(r) : "f"(lo), "f"(hi)); return r;
}
__device__ __forceinline__ void unpack2(ull v, float& lo, float& hi) {
    asm("mov.b64 {%0, %1}, %2;" : "=f"(lo), "=f"(hi) : "l"(v));
}
__device__ __forceinline__ ull fma2(ull a, ull b, ull c) {
    ull d; asm("fma.rn.f32x2 %0, %1, %2, %3;" : "=l"(d) : "l"(a), "l"(b), "l"(c));
    return d;
}
__device__ __forceinline__ ull mul2(ull a, ull b) {
    ull d; asm("mul.rn.f32x2 %0, %1, %2;" : "=l"(d) : "l"(a), "l"(b));
    return d;
}
__device__ __forceinline__ float hsum2(ull v) {
    float lo, hi; unpack2(v, lo, hi); return lo + hi;
}

// One WARP per 64x64 SPD matrix.
// Phase 1: PIVOTED in-warp Cholesky P A P^T = L L^T (Drmac-Veselic). The
//   argmax reduce breaks ties on the smaller index so `bi` is WARP-UNIFORM
//   (round 15 crashed: strict > left lanes with different bi under ties ->
//   divergent branch around __syncwarp = UB, and inconsistent swaps).
// Phase 2: one-sided Jacobi on the columns of L (round-12 loop verbatim).
// Phase 3: epilogue scatters W's rows through perm[] (undoes P for free).
__global__ void __launch_bounds__(32, 12)
logeig_pchol_jacobi_kernel(const float* __restrict__ x, float* __restrict__ out)
{
    __shared__ float Uw[N][N + 1];
    __shared__ float w[N];
    __shared__ int   perm[N];   // perm[pos] = original index at position pos

    const int lane = threadIdx.x;
    const size_t base = (size_t)blockIdx.x * (N * N);
    const float* __restrict__ xin = x + base;
    float* __restrict__ o = out + base;

    // ---- load A into shared (row-major), init perm
    for (int idx = lane; idx < N * N; idx += 32)
        Uw[idx >> 6][idx & 63] = xin[idx];
    perm[lane] = lane;
    perm[NH + lane] = NH + lane;
    __syncwarp();

    // ---- in-place pivoted Cholesky (full-square symmetric trailing update)
    for (int k = 0; k < N - 1; ++k) {
        // -- pivot: warp-uniform argmax of remaining diagonal (tie -> min idx)
        {
            int i0 = k + lane, i1 = k + lane + 32;
            float v0 = (i0 < N) ? Uw[i0][i0] : -1.0f;
            float v1 = (i1 < N) ? Uw[i1][i1] : -1.0f;
            int   bi;
            float bv;
            if (v1 > v0) { bv = v1; bi = i1; } else { bv = v0; bi = i0; }
            #pragma unroll
            for (int off = 16; off; off >>= 1) {
                float ov = __shfl_xor_sync(FULLMASK, bv, off);
                int   oi = __shfl_xor_sync(FULLMASK, bi, off);
                if (ov > bv || (ov == bv && oi < bi)) { bv = ov; bi = oi; }
            }
            // bi is now identical in every lane -> uniform branch below
            if (bi != k) {
                int j0 = lane, j1 = lane + 32;
                float ra = Uw[k][j0], rb = Uw[bi][j0];
                Uw[k][j0] = rb;  Uw[bi][j0] = ra;
                ra = Uw[k][j1];  rb = Uw[bi][j1];
                Uw[k][j1] = rb;  Uw[bi][j1] = ra;
                __syncwarp();
                ra = Uw[j0][k];  rb = Uw[j0][bi];
                Uw[j0][k] = rb;  Uw[j0][bi] = ra;
                ra = Uw[j1][k];  rb = Uw[j1][bi];
                Uw[j1][k] = rb;  Uw[j1][bi] = ra;
                if (lane == 0) { int t = perm[k]; perm[k] = perm[bi]; perm[bi] = t; }
                __syncwarp();
            }
        }

        float d = Uw[k][k];
        float inv = rsqrtf(d);
        const int i0 = k + 1 + lane;
        const int i1 = i0 + 32;
        float l0 = 0.0f, l1 = 0.0f;
        if (i0 < N) { l0 = Uw[i0][k] * inv; Uw[i0][k] = l0; }
        if (i1 < N) { l1 = Uw[i1][k] * inv; Uw[i1][k] = l1; }
        if (lane == 0) Uw[k][k] = d * inv;            // sqrt(d)
        __syncwarp();
        if (i0 < N) {
            if (i1 < N) {
                for (int j = k + 1; j < N; ++j) {
                    float ljk = Uw[j][k];              // broadcast
                    Uw[i0][j] = fmaf(-l0, ljk, Uw[i0][j]);
                    Uw[i1][j] = fmaf(-l1, ljk, Uw[i1][j]);
                }
            } else {
                for (int j = k + 1; j < N; ++j) {
                    float ljk = Uw[j][k];
                    Uw[i0][j] = fmaf(-l0, ljk, Uw[i0][j]);
                }
            }
        }
        __syncwarp();
    }
    if (lane == 0) Uw[N - 1][N - 1] = sqrtf(Uw[N - 1][N - 1]);
    __syncwarp();

    // ---- load L columns into registers (zero above the diagonal)
    ull top2[NP], bot2[NP];   // columns in slots (lane) and (32+lane)
    const int cb = NH + lane;
    #pragma unroll
    for (int j = 0; j < NP; ++j) {
        const int r0 = 2 * j, r1 = 2 * j + 1;
        float a0 = (r0 >= lane) ? Uw[r0][lane] : 0.0f;
        float a1 = (r1 >= lane) ? Uw[r1][lane] : 0.0f;
        float b0 = (r0 >= cb)   ? Uw[r0][cb]   : 0.0f;
        float b1 = (r1 >= cb)   ? Uw[r1][cb]   : 0.0f;
        top2[j] = pack2(a0, a1);
        bot2[j] = pack2(b0, b1);
    }
    __syncwarp();

    // ---- one-sided Jacobi on L's columns (round-12 loop, verbatim)
    for (int sweep = 0; sweep < NSWEEPS_MAX; ++sweep) {
        // fresh full Gram of the owned pair at sweep start (resync)
        float app, apq, aqq;
        {
            ull sp = 0ull, sx = 0ull, sq = 0ull;
            #pragma unroll
            for (int j = 0; j < NP; ++j) {
                ull t2 = top2[j], b2 = bot2[j];
                sp = fma2(t2, t2, sp);
                sx = fma2(t2, b2, sx);
                sq = fma2(b2, b2, sq);
            }
            app = hsum2(sp);
            apq = hsum2(sx);
            aqq = hsum2(sq);
        }

        bool bad = false;
        for (int r = 0; r < N - 1; ++r) {
            bad = bad || (apq * apq > CONV_TOL * (app * aqq));

            // Jacobi rotation from the 2x2 Gram
            float c = 1.0f, s = 0.0f, t = 0.0f;
            if (fabsf(apq) > 1e-30f) {
                float theta = __fdividef(0.5f * (aqq - app), apq);
                t = copysignf(1.0f, theta) /
                    (fabsf(theta) + sqrtf(fmaf(theta, theta, 1.0f)));
                c = rsqrtf(fmaf(t, t, 1.0f));
                s = t * c;
            }
            const ull cc = pack2(c, c);
            const ull ss = pack2(s, s);
            const ull ns = pack2(-s, -s);

            // rotate + ring-shift (circle method), fusing next round's apq
            ull sxn = 0ull;
            #pragma unroll
            for (int j = 0; j < NP; ++j) {
                ull t2 = top2[j], b2 = bot2[j];
                ull rt = fma2(cc, t2, mul2(ns, b2));    // c*top - s*bot
                ull rb = fma2(ss, t2, mul2(cc, b2));    // s*top + c*bot
                ull tsel = (lane == 0) ? rb : rt;
                ull tup  = __shfl_up_sync(FULLMASK, tsel, 1);
                ull ntv  = (lane == 0) ? rt : tup;
                ull bdn  = __shfl_down_sync(FULLMASK, rb, 1);
                ull nbv  = (lane == 31) ? rt : bdn;
                top2[j] = ntv;
                bot2[j] = nbv;
                sxn = fma2(ntv, nbv, sxn);
            }

            // maintained norms (exact identity) + same ring shift
            float app2 = fmaf(-t, apq, app);
            float aqq2 = fmaf( t, apq, aqq);
            float nsel = (lane == 0) ? aqq2 : app2;
            float nup  = __shfl_up_sync(FULLMASK, nsel, 1);
            app        = (lane == 0) ? app2 : nup;
            float ndn  = __shfl_down_sync(FULLMASK, aqq2, 1);
            aqq        = (lane == 31) ? app2 : ndn;

            apq = hsum2(sxn);
        }

        if (!__any_sync(FULLMASK, bad)) break;
    }

    // ---- final fresh squared norms -> weights w = log(n)/n, n = sigma^2 = lambda
    {
        ull sp = 0ull, sq = 0ull;
        #pragma unroll
        for (int j = 0; j < NP; ++j) {
            sp = fma2(top2[j], top2[j], sp);
            sq = fma2(bot2[j], bot2[j], sq);
        }
        float nt = hsum2(sp);
        float nb = hsum2(sq);
        w[lane] = logf(fmaxf(nt, 1e-38f)) / nt;
        w[cb]   = logf(fmaxf(nb, 1e-38f)) / nb;
    }

    // ---- publish W to shared, undoing the pivot permutation on rows:
    //      log(A) = P^T M P  <=>  scatter W row r to shared row perm[r]
    #pragma unroll
    for (int j = 0; j < NP; ++j) {
        float a0, a1, b0, b1;
        unpack2(top2[j], a0, a1);
        unpack2(bot2[j], b0, b1);
        const int p0 = perm[2 * j], p1 = perm[2 * j + 1];   // broadcast reads
        Uw[p0][lane] = a0;
        Uw[p1][lane] = a1;
        Uw[p0][cb]   = b0;
        Uw[p1][cb]   = b1;
    }
    __syncwarp();

    // ---- out = sum_k w_k u_k u_k^T ; lane computes output columns (2*lane, 2*lane+1)
    #pragma unroll
    for (int j = 0; j < NP; ++j) { top2[j] = 0ull; bot2[j] = 0ull; }
    const int j0 = 2 * lane;
    for (int k = 0; k < N; ++k) {
        float wk = w[k];
        float a0 = wk * Uw[j0][k];
        float a1 = wk * Uw[j0 + 1][k];
        ull aa0 = pack2(a0, a0);
        ull aa1 = pack2(a1, a1);
        #pragma unroll
        for (int j = 0; j < NP; ++j) {
            ull vv = pack2(Uw[2 * j][k], Uw[2 * j + 1][k]);   // broadcast loads
            top2[j] = fma2(aa0, vv, top2[j]);
            bot2[j] = fma2(aa1, vv, bot2[j]);
        }
    }
    // rows 2j / 2j+1, columns (j0, j0+1) contiguous -> coalesced float2 stores
    #pragma unroll
    for (int j = 0; j < NP; ++j) {
        float t0, t1, b0, b1;
        unpack2(top2[j], t0, t1);
        unpack2(bot2[j], b0, b1);
        *reinterpret_cast<float2*>(o + (2 * j) * N + j0)     = make_float2(t0, b0);
        *reinterpret_cast<float2*>(o + (2 * j + 1) * N + j0) = make_float2(t1, b1);
    }
}

extern "C" void kernel_launch(void* const* d_in, const int* in_sizes, int n_in,
                              void* d_out, int out_size) {
    const float* x = (const float*)d_in[0];
    float* out = (float*)d_out;
    int B = in_sizes[0] / (N * N);   // 8192
    logeig_pchol_jacobi_kernel<<<B, 32>>>(x, out);
}

// round 17
// speedup vs baseline: 1.7501x; 1.7501x over previous
#include <cuda_runtime.h>
#include <math.h>

#define NSWEEPS_MAX 16
#define N 64
#define NH 32
#define NP 32            // packed row-pairs per column
#define FULLMASK 0xffffffffu
#define CONV_TOL 1e-5f   // predictive: max pre-rotation apq^2/(app*aqq) < tol
                         // => this sweep's rotations leave residual ~tol^2,
                         // so exit WITHOUT a separate detection sweep.

typedef unsigned long long ull;

__device__ __forceinline__ ull pack2(float lo, float hi) {
    ull r; asm("mov.b64 %0, {%1, %2};" : "=l"(r) : "f"(lo), "f"(hi)); return r;
}
__device__ __forceinline__ void unpack2(ull v, float& lo, float& hi) {
    asm("mov.b64 {%0, %1}, %2;" : "=f"(lo), "=f"(hi) : "l"(v));
}
__device__ __forceinline__ ull fma2(ull a, ull b, ull c) {
    ull d; asm("fma.rn.f32x2 %0, %1, %2, %3;" : "=l"(d) : "l"(a), "l"(b), "l"(c));
    return d;
}
__device__ __forceinline__ ull mul2(ull a, ull b) {
    ull d; asm("mul.rn.f32x2 %0, %1, %2;" : "=l"(d) : "l"(a), "l"(b));
    return d;
}
__device__ __forceinline__ float hsum2(ull v) {
    float lo, hi; unpack2(v, lo, hi); return lo + hi;
}

// One WARP per 64x64 SPD matrix.
// Phase 1: in-warp (unpivoted) Cholesky A = L L^T in shared — round-14
//   champion structure; pivoting (round 16) spilled registers and bought no
//   sweep reduction, so it is dropped.
// Phase 2: one-sided Jacobi on the columns of L, with PREDICTIVE exit: when
//   a sweep's worst pre-rotation apq^2/(app*aqq) < CONV_TOL=1e-5, quadratic
//   convergence guarantees this sweep's rotations finish the job (residual
//   ~64*tol^2 ~ 6e-9) — exit immediately, saving the old detection sweep.
// Phase 3: epilogue: W = U*Sigma, |w_k|^2 = lambda_k,
//   log(A) = sum_k (log n_k / n_k) w_k w_k^T,  n_k = |w_k|^2.
__global__ void __launch_bounds__(32, 12)
logeig_chol_jacobi_kernel(const float* __restrict__ x, float* __restrict__ out)
{
    __shared__ float Uw[N][N + 1];
    __shared__ float w[N];

    const int lane = threadIdx.x;
    const size_t base = (size_t)blockIdx.x * (N * N);
    const float* __restrict__ xin = x + base;
    float* __restrict__ o = out + base;

    // ---- load A into shared (row-major)
    for (int idx = lane; idx < N * N; idx += 32)
        Uw[idx >> 6][idx & 63] = xin[idx];
    __syncwarp();

    // ---- in-place Cholesky (lower triangle; full-square symmetric update)
    for (int k = 0; k < N - 1; ++k) {
        float d = Uw[k][k];
        float inv = rsqrtf(d);
        const int i0 = k + 1 + lane;
        const int i1 = i0 + 32;
        float l0 = 0.0f, l1 = 0.0f;
        if (i0 < N) { l0 = Uw[i0][k] * inv; Uw[i0][k] = l0; }
        if (i1 < N) { l1 = Uw[i1][k] * inv; Uw[i1][k] = l1; }
        if (lane == 0) Uw[k][k] = d * inv;            // sqrt(d)
        __syncwarp();
        if (i0 < N) {
            if (i1 < N) {
                for (int j = k + 1; j < N; ++j) {
                    float ljk = Uw[j][k];              // broadcast
                    Uw[i0][j] = fmaf(-l0, ljk, Uw[i0][j]);
                    Uw[i1][j] = fmaf(-l1, ljk, Uw[i1][j]);
                }
            } else {
                for (int j = k + 1; j < N; ++j) {
                    float ljk = Uw[j][k];
                    Uw[i0][j] = fmaf(-l0, ljk, Uw[i0][j]);
                }
            }
        }
        __syncwarp();
    }
    if (lane == 0) Uw[N - 1][N - 1] = sqrtf(Uw[N - 1][N - 1]);
    __syncwarp();

    // ---- load L columns into registers (zero above the diagonal)
    ull top2[NP], bot2[NP];   // columns in slots (lane) and (32+lane)
    const int cb = NH + lane;
    #pragma unroll
    for (int j = 0; j < NP; ++j) {
        const int r0 = 2 * j, r1 = 2 * j + 1;
        float a0 = (r0 >= lane) ? Uw[r0][lane] : 0.0f;
        float a1 = (r1 >= lane) ? Uw[r1][lane] : 0.0f;
        float b0 = (r0 >= cb)   ? Uw[r0][cb]   : 0.0f;
        float b1 = (r1 >= cb)   ? Uw[r1][cb]   : 0.0f;
        top2[j] = pack2(a0, a1);
        bot2[j] = pack2(b0, b1);
    }
    __syncwarp();

    // ---- one-sided Jacobi on L's columns (round-12 loop, verbatim)
    for (int sweep = 0; sweep < NSWEEPS_MAX; ++sweep) {
        // fresh full Gram of the owned pair at sweep start (resync)
        float app, apq, aqq;
        {
            ull sp = 0ull, sx = 0ull, sq = 0ull;
            #pragma unroll
            for (int j = 0; j < NP; ++j) {
                ull t2 = top2[j], b2 = bot2[j];
                sp = fma2(t2, t2, sp);
                sx = fma2(t2, b2, sx);
                sq = fma2(b2, b2, sq);
            }
            app = hsum2(sp);
            apq = hsum2(sx);
            aqq = hsum2(sq);
        }

        bool bad = false;
        for (int r = 0; r < N - 1; ++r) {
            bad = bad || (apq * apq > CONV_TOL * (app * aqq));

            // Jacobi rotation from the 2x2 Gram
            float c = 1.0f, s = 0.0f, t = 0.0f;
            if (fabsf(apq) > 1e-30f) {
                float theta = __fdividef(0.5f * (aqq - app), apq);
                t = copysignf(1.0f, theta) /
                    (fabsf(theta) + sqrtf(fmaf(theta, theta, 1.0f)));
                c = rsqrtf(fmaf(t, t, 1.0f));
                s = t * c;
            }
            const ull cc = pack2(c, c);
            const ull ss = pack2(s, s);
            const ull ns = pack2(-s, -s);

            // rotate + ring-shift (circle method), fusing next round's apq
            ull sxn = 0ull;
            #pragma unroll
            for (int j = 0; j < NP; ++j) {
                ull t2 = top2[j], b2 = bot2[j];
                ull rt = fma2(cc, t2, mul2(ns, b2));    // c*top - s*bot
                ull rb = fma2(ss, t2, mul2(cc, b2));    // s*top + c*bot
                ull tsel = (lane == 0) ? rb : rt;
                ull tup  = __shfl_up_sync(FULLMASK, tsel, 1);
                ull ntv  = (lane == 0) ? rt : tup;
                ull bdn  = __shfl_down_sync(FULLMASK, rb, 1);
                ull nbv  = (lane == 31) ? rt : bdn;
                top2[j] = ntv;
                bot2[j] = nbv;
                sxn = fma2(ntv, nbv, sxn);
            }

            // maintained norms (exact identity) + same ring shift
            float app2 = fmaf(-t, apq, app);
            float aqq2 = fmaf( t, apq, aqq);
            float nsel = (lane == 0) ? aqq2 : app2;
            float nup  = __shfl_up_sync(FULLMASK, nsel, 1);
            app        = (lane == 0) ? app2 : nup;
            float ndn  = __shfl_down_sync(FULLMASK, aqq2, 1);
            aqq        = (lane == 31) ? app2 : ndn;

            apq = hsum2(sxn);
        }

        if (!__any_sync(FULLMASK, bad)) break;
    }

    // ---- final fresh squared norms -> weights w = log(n)/n, n = sigma^2 = lambda
    {
        ull sp = 0ull, sq = 0ull;
        #pragma unroll
        for (int j = 0; j < NP; ++j) {
            sp = fma2(top2[j], top2[j], sp);
            sq = fma2(bot2[j], bot2[j], sq);
        }
        float nt = hsum2(sp);
        float nb = hsum2(sq);
        w[lane] = logf(fmaxf(nt, 1e-38f)) / nt;
        w[cb]   = logf(fmaxf(nb, 1e-38f)) / nb;
    }

    // ---- publish W to shared
    #pragma unroll
    for (int j = 0; j < NP; ++j) {
        float a0, a1, b0, b1;
        unpack2(top2[j], a0, a1);
        unpack2(bot2[j], b0, b1);
        Uw[2 * j][lane]     = a0;
        Uw[2 * j + 1][lane] = a1;
        Uw[2 * j][cb]       = b0;
        Uw[2 * j + 1][cb]   = b1;
    }
    __syncwarp();

    // ---- out = sum_k w_k u_k u_k^T ; lane computes output columns (2*lane, 2*lane+1)
    #pragma unroll
    for (int j = 0; j < NP; ++j) { top2[j] = 0ull; bot2[j] = 0ull; }
    const int j0 = 2 * lane;
    for (int k = 0; k < N; ++k) {
        float wk = w[k];
        float a0 = wk * Uw[j0][k];
        float a1 = wk * Uw[j0 + 1][k];
        ull aa0 = pack2(a0, a0);
        ull aa1 = pack2(a1, a1);
        #pragma unroll
        for (int j = 0; j < NP; ++j) {
            ull vv = pack2(Uw[2 * j][k], Uw[2 * j + 1][k]);   // broadcast loads
            top2[j] = fma2(aa0, vv, top2[j]);
            bot2[j] = fma2(aa1, vv, bot2[j]);
        }
    }
    // rows 2j / 2j+1, columns (j0, j0+1) contiguous -> coalesced float2 stores
    #pragma unroll
    for (int j = 0; j < NP; ++j) {
        float t0, t1, b0, b1;
        unpack2(top2[j], t0, t1);
        unpack2(bot2[j], b0, b1);
        *reinterpret_cast<float2*>(o + (2 * j) * N + j0)     = make_float2(t0, b0);
        *reinterpret_cast<float2*>(o + (2 * j + 1) * N + j0) = make_float2(t1, b1);
    }
}

extern "C" void kernel_launch(void* const* d_in, const int* in_sizes, int n_in,
                              void* d_out, int out_size) {
    const float* x = (const float*)d_in[0];
    float* out = (float*)d_out;
    int B = in_sizes[0] / (N * N);   // 8192
    logeig_chol_jacobi_kernel<<<B, 32>>>(x, out);
}